// round 8
// baseline (speedup 1.0000x reference)
#include <cuda_runtime.h>
#include <cuda_fp16.h>
#include <cstdint>

// Problem dims
#define BB 64
#define RR 50
#define LL 15
#define DD 1024
#define FF 4096

// GEMM: M=B*R=3200, N=D=1024, K=F=4096
#define GM 3200
#define GN 1024
#define GK 4096

// CTA tile 128x128x64 (fp16), split-K=2 -> grid (8, 25, 2) = 400 CTAs.
#define BM 128
#define BN 128
#define BK 64
#define KSPLIT 2
#define KHALF (GK / KSPLIT)         // 2048
#define NIT (KHALF / BK)            // 32
#define APH 72                      // padded row stride in halves (144B, conflict-free)
#define STAGES 4
#define A_STAGE_BYTES (BM * APH * 2)          // 18432
#define STAGE_BYTES (2 * BM * APH * 2)        // 36864 (A + B)
#define SMEM_TOTAL (STAGES * STAGE_BYTES)     // 147456
#define NTHREADS 256

// pooling fused into GEMM: 400 CTAs x 8 rows, 120 row-steps, 4 per iteration
#define PROWS 8
#define PSTEPS (PROWS * LL)          // 120
#define PGROUP 4

// W fp16 copy; split partial scratch; 1/len; tile arrival counters
__device__ __half g_Wh[GN * GK];
__device__ float g_part0[GM * GN];
__device__ float g_part1[GM * GN];
__device__ float g_invlen[GM];
__device__ int g_cnt[256];   // zero-init; returns to 0 every launch

__device__ __forceinline__ void mma_f16(float& c0, float& c1, float& c2, float& c3,
                                        uint32_t a0, uint32_t a1, uint32_t a2, uint32_t a3,
                                        uint32_t b0, uint32_t b1) {
    asm volatile(
        "mma.sync.aligned.m16n8k16.row.col.f32.f16.f16.f32 "
        "{%0,%1,%2,%3}, {%4,%5,%6,%7}, {%8,%9}, {%0,%1,%2,%3};\n"
        : "+f"(c0), "+f"(c1), "+f"(c2), "+f"(c3)
        : "r"(a0), "r"(a1), "r"(a2), "r"(a3), "r"(b0), "r"(b1));
}

__device__ __forceinline__ uint32_t smem_u32(const void* p) {
    uint32_t a;
    asm("{ .reg .u64 t; cvta.to.shared.u64 t, %1; cvt.u32.u64 %0, t; }" : "=r"(a) : "l"(p));
    return a;
}

__device__ __forceinline__ uint32_t packh2(float a, float b) {
    __half2 h = __floats2half2_rn(a, b);
    return *(uint32_t*)&h;
}

#define CP_ASYNC16(dst, src) \
    asm volatile("cp.async.cg.shared.global [%0], [%1], 16;" :: "r"(dst), "l"(src) : "memory")
#define CP_COMMIT() asm volatile("cp.async.commit_group;" ::: "memory")
#define CP_WAIT(n) asm volatile("cp.async.wait_group %0;" :: "n"(n) : "memory")

#define LDSM4(r0, r1, r2, r3, addr) \
    asm volatile("ldmatrix.sync.aligned.m8n8.x4.shared.b16 {%0,%1,%2,%3}, [%4];" \
                 : "=r"(r0), "=r"(r1), "=r"(r2), "=r"(r3) : "r"(addr))

#define STS128(addr, v0, v1, v2, v3) \
    asm volatile("st.shared.v4.b32 [%0], {%1,%2,%3,%4};" \
                 :: "r"(addr), "r"(v0), "r"(v1), "r"(v2), "r"(v3) : "memory")

// ─────────────────── prepass: W fp32 -> fp16(rna), plus 1/len ───────────────────
__global__ void __launch_bounds__(256)
cvt_w_kernel(const float* __restrict__ W, const int* __restrict__ lens) {
    const int gid = blockIdx.x * blockDim.x + threadIdx.x;
    if (gid < GM) g_invlen[gid] = 1.0f / (float)__ldg(lens + gid);

    const int nw8 = GN * GK / 8;   // 16B output chunks
    for (int i = gid; i < nw8; i += gridDim.x * blockDim.x) {
        const float4* src = (const float4*)W + (size_t)i * 2;
        float4 v0 = __ldg(src);
        float4 v1 = __ldg(src + 1);
        uint4 o4;
        o4.x = packh2(v0.x, v0.y);
        o4.y = packh2(v0.z, v0.w);
        o4.z = packh2(v1.x, v1.y);
        o4.w = packh2(v1.z, v1.w);
        *((uint4*)g_Wh + i) = o4;
    }
}

// ── GEMM partials (A converted in-kernel), split-K=2, fused mean-pool + fused reduce ──
__global__ void __launch_bounds__(NTHREADS, 1)
gemm_fused_kernel(const float* __restrict__ Afp, const float* __restrict__ phrases,
                  const float* __restrict__ bias, float* __restrict__ out) {
    extern __shared__ char smem[];
    const uint32_t sb = smem_u32(smem);

    const int tid = threadIdx.x;
    const int warp = tid >> 5;      // 0..7
    const int lane = tid & 31;
    const int warp_m = warp & 1;    // 0..1 -> 64-row slab
    const int warp_n = warp >> 1;   // 0..3 -> 32-col slab
    const int m0 = blockIdx.y * BM;
    const int n0 = blockIdx.x * BN;
    const int kbase = blockIdx.z * KHALF;

    // pooling assignment
    const int cid = blockIdx.z * (GN / BN) * (GM / BM) + blockIdx.y * (GN / BN) + blockIdx.x;
    const int prow0 = cid * PROWS;
    const float4* pf = (const float4*)(phrases + (size_t)prow0 * LL * DD) + tid;

    // B cp.async mapping: tile = 128 rows x 8 16B-chunks; 4 per thread
    uint32_t b_dst[4];
    const __half* b_src[4];
#pragma unroll
    for (int i = 0; i < 4; i++) {
        int id = tid + i * NTHREADS;
        int row = id >> 3, c8 = id & 7;
        b_dst[i] = A_STAGE_BYTES + row * (APH * 2) + c8 * 16;
        b_src[i] = g_Wh + (size_t)(n0 + row) * GK + kbase + c8 * 8;
    }

    // A fp32 direct-convert staging: thread -> (row, half-row), 32 consecutive floats
    const int ar = tid >> 1;
    const int ah = tid & 1;
    const float* aG = Afp + (size_t)(m0 + ar) * GK + kbase + ah * 32;
    const uint32_t a_sts = ar * (APH * 2) + ah * 64;

    // ldmatrix lane bases
    const int la_row = (lane & 7) + ((lane >> 3) & 1) * 8;
    const uint32_t pA_base = ((warp_m * 64 + la_row) * APH + (lane >> 4) * 8) * 2;
    const int lb_row = (lane & 7) + ((lane >> 4) & 1) * 8;
    const uint32_t pB_base =
        A_STAGE_BYTES + ((warp_n * 32 + lb_row) * APH + ((lane >> 3) & 1) * 8) * 2;

    float acc[4][4][4];
#pragma unroll
    for (int tm = 0; tm < 4; tm++)
#pragma unroll
        for (int tn = 0; tn < 4; tn++)
#pragma unroll
            for (int r = 0; r < 4; r++) acc[tm][tn][r] = 0.0f;

    // preload: B via cp.async for stages 0..2; A via LDG+cvt+STS for stages 0..2
#pragma unroll
    for (int s = 0; s < STAGES - 1; s++) {
        const uint32_t st = sb + s * STAGE_BYTES;
        const int k0 = s * BK;
#pragma unroll
        for (int i = 0; i < 4; i++) CP_ASYNC16(st + b_dst[i], b_src[i] + k0);
        CP_COMMIT();

        float4 t[8];
        const float4* asrc = (const float4*)(aG + s * BK);
#pragma unroll
        for (int j = 0; j < 8; j++) t[j] = __ldg(asrc + j);
        const uint32_t ad = st + a_sts;
#pragma unroll
        for (int q = 0; q < 4; q++)
            STS128(ad + q * 16,
                   packh2(t[2 * q].x, t[2 * q].y), packh2(t[2 * q].z, t[2 * q].w),
                   packh2(t[2 * q + 1].x, t[2 * q + 1].y), packh2(t[2 * q + 1].z, t[2 * q + 1].w));
    }

    // A register staging for chunk 3
    float4 abuf[8];
    {
        const float4* asrc = (const float4*)(aG + 3 * BK);
#pragma unroll
        for (int j = 0; j < 8; j++) abuf[j] = __ldg(asrc + j);
    }

    // pool state
    float4 pbuf[PGROUP];
#pragma unroll
    for (int j = 0; j < PGROUP; j++) pbuf[j] = __ldg(pf + j * (DD / 4));
    float pacc0 = 0.f, pacc1 = 0.f, pacc2 = 0.f, pacc3 = 0.f;
    float pinv = 0.f;
    int parow = 0, ppl = 0;

    uint32_t af[2][4][4], bf[2][4][2];

    for (int it = 0; it < NIT; it++) {
        CP_WAIT(STAGES - 2);
        __syncthreads();

        // B loads for stage it+3
        {
            const int ld = it + STAGES - 1;
            if (ld < NIT) {
                const uint32_t st = sb + (ld & (STAGES - 1)) * STAGE_BYTES;
                const int k0 = ld * BK;
#pragma unroll
                for (int i = 0; i < 4; i++) CP_ASYNC16(st + b_dst[i], b_src[i] + k0);
            }
            CP_COMMIT();
        }

        // A STS for stage it+3 (data prefetched last iteration), then LDG chunk it+4
        if (it + 3 < NIT) {
            const uint32_t ad = sb + ((it + 3) & (STAGES - 1)) * STAGE_BYTES + a_sts;
#pragma unroll
            for (int q = 0; q < 4; q++)
                STS128(ad + q * 16,
                       packh2(abuf[2 * q].x, abuf[2 * q].y), packh2(abuf[2 * q].z, abuf[2 * q].w),
                       packh2(abuf[2 * q + 1].x, abuf[2 * q + 1].y),
                       packh2(abuf[2 * q + 1].z, abuf[2 * q + 1].w));
        }
        if (it + 4 < NIT) {
            const float4* asrc = (const float4*)(aG + (it + 4) * BK);
#pragma unroll
            for (int j = 0; j < 8; j++) abuf[j] = __ldg(asrc + j);
        }

        // fused pooling: accumulate group `it`, prefetch group it+1
        if (it * PGROUP < PSTEPS) {
#pragma unroll
            for (int j = 0; j < PGROUP; j++) {
                if (ppl == 0) pinv = __ldg(g_invlen + prow0 + parow);
                pacc0 += pbuf[j].x; pacc1 += pbuf[j].y;
                pacc2 += pbuf[j].z; pacc3 += pbuf[j].w;
                ppl++;
                if (ppl == LL) {
                    float4 r = make_float4(pacc0 * pinv, pacc1 * pinv, pacc2 * pinv, pacc3 * pinv);
                    *((float4*)(out + (size_t)(prow0 + parow) * (2 * GN) + GN) + tid) = r;
                    pacc0 = pacc1 = pacc2 = pacc3 = 0.f;
                    ppl = 0;
                    parow++;
                }
            }
            const int sbase = (it + 1) * PGROUP;
            if (sbase < PSTEPS) {
#pragma unroll
                for (int j = 0; j < PGROUP; j++)
                    pbuf[j] = __ldg(pf + (sbase + j) * (DD / 4));
            }
        }

        const uint32_t st = sb + (it & (STAGES - 1)) * STAGE_BYTES;
        const uint32_t aA = st + pA_base;
        const uint32_t aB = st + pB_base;

        // prefetch fragments for ks=0
#pragma unroll
        for (int tm = 0; tm < 4; tm++)
            LDSM4(af[0][tm][0], af[0][tm][1], af[0][tm][2], af[0][tm][3],
                  aA + (tm * 16 * APH) * 2);
#pragma unroll
        for (int pr = 0; pr < 2; pr++)
            LDSM4(bf[0][pr * 2][0], bf[0][pr * 2][1], bf[0][pr * 2 + 1][0], bf[0][pr * 2 + 1][1],
                  aB + (pr * 16 * APH) * 2);

        // 4 k16-steps, register double-buffered
#pragma unroll
        for (int ks = 0; ks < 4; ks++) {
            const int cur = ks & 1, nxt = cur ^ 1;
            if (ks < 3) {
                const uint32_t ko = (ks + 1) * 32;
#pragma unroll
                for (int tm = 0; tm < 4; tm++)
                    LDSM4(af[nxt][tm][0], af[nxt][tm][1], af[nxt][tm][2], af[nxt][tm][3],
                          aA + (tm * 16 * APH) * 2 + ko);
#pragma unroll
                for (int pr = 0; pr < 2; pr++)
                    LDSM4(bf[nxt][pr * 2][0], bf[nxt][pr * 2][1],
                          bf[nxt][pr * 2 + 1][0], bf[nxt][pr * 2 + 1][1],
                          aB + (pr * 16 * APH) * 2 + ko);
            }
#pragma unroll
            for (int tm = 0; tm < 4; tm++)
#pragma unroll
                for (int tn = 0; tn < 4; tn++)
                    mma_f16(acc[tm][tn][0], acc[tm][tn][1], acc[tm][tn][2], acc[tm][tn][3],
                            af[cur][tm][0], af[cur][tm][1], af[cur][tm][2], af[cur][tm][3],
                            bf[cur][tn][0], bf[cur][tn][1]);
        }
    }

    // write raw partial to split scratch
    float* pdst = (blockIdx.z == 0) ? g_part0 : g_part1;
#pragma unroll
    for (int tn = 0; tn < 4; tn++) {
        const int n = n0 + warp_n * 32 + tn * 8 + (lane & 3) * 2;
#pragma unroll
        for (int tm = 0; tm < 4; tm++) {
            const int r0 = m0 + warp_m * 64 + tm * 16 + (lane >> 2);
            *(float2*)(pdst + (size_t)r0 * GN + n) = make_float2(acc[tm][tn][0], acc[tm][tn][1]);
            *(float2*)(pdst + (size_t)(r0 + 8) * GN + n) = make_float2(acc[tm][tn][2], acc[tm][tn][3]);
        }
    }

    // fused split-K reduce: second finisher per tile does relu(p0+p1+b) -> out
    __threadfence();
    __syncthreads();
    int* flag = (int*)smem;
    const int tile = blockIdx.y * (GN / BN) + blockIdx.x;
    if (tid == 0) {
        int old = atomicAdd(&g_cnt[tile], 1);
        *flag = (old == 1);
    }
    __syncthreads();
    if (*flag) {
        __threadfence();  // acquire side
#pragma unroll
        for (int i = 0; i < 16; i++) {
            int idx = tid + i * NTHREADS;        // 0..4095 float4s of the 128x128 tile
            int row = idx >> 5, c4 = idx & 31;
            size_t po = (size_t)(m0 + row) * GN + n0 + c4 * 4;
            float4 p0 = *(const float4*)(g_part0 + po);
            float4 p1 = *(const float4*)(g_part1 + po);
            float4 bv = __ldg((const float4*)(bias + n0) + c4);
            float4 v;
            v.x = fmaxf(p0.x + p1.x + bv.x, 0.0f);
            v.y = fmaxf(p0.y + p1.y + bv.y, 0.0f);
            v.z = fmaxf(p0.z + p1.z + bv.z, 0.0f);
            v.w = fmaxf(p0.w + p1.w + bv.w, 0.0f);
            *(float4*)(out + (size_t)(m0 + row) * (2 * GN) + n0 + c4 * 4) = v;
        }
        if (tid == 0) g_cnt[tile] = 0;   // reset for next launch/replay
    }
}

extern "C" void kernel_launch(void* const* d_in, const int* in_sizes, int n_in,
                              void* d_out, int out_size) {
    const float* features = (const float*)d_in[0];
    const float* phrases  = (const float*)d_in[1];
    const float* W        = (const float*)d_in[2];
    const float* bias     = (const float*)d_in[3];
    const int*   lens     = (const int*)d_in[4];
    float* out = (float*)d_out;

    cvt_w_kernel<<<1024, 256>>>(W, lens);

    cudaFuncSetAttribute(gemm_fused_kernel, cudaFuncAttributeMaxDynamicSharedMemorySize,
                         SMEM_TOTAL);
    dim3 ggrid(GN / BN, GM / BM, KSPLIT);  // (8, 25, 2) = 400 CTAs
    gemm_fused_kernel<<<ggrid, NTHREADS, SMEM_TOTAL>>>(features, phrases, bias, out);
}

// round 9
// speedup vs baseline: 1.7965x; 1.7965x over previous
#include <cuda_runtime.h>
#include <cuda_fp16.h>
#include <cstdint>

// Problem dims
#define BB 64
#define RR 50
#define LL 15
#define DD 1024
#define FF 4096

// GEMM: M=B*R=3200, N=D=1024, K=F=4096
#define GM 3200
#define GN 1024
#define GK 4096

// CTA tile 128x128x64 (fp16), split-K=2 -> grid (8, 25, 2) = 400 CTAs.
#define BM 128
#define BN 128
#define BK 64
#define KSPLIT 2
#define KHALF (GK / KSPLIT)         // 2048
#define NIT (KHALF / BK)            // 32
#define APH 72                      // padded row stride in halves (144B, conflict-free)
#define STAGES 4
#define A_STAGE_BYTES (BM * APH * 2)          // 18432
#define STAGE_BYTES (2 * BM * APH * 2)        // 36864 (A + B)
#define SMEM_TOTAL (STAGES * STAGE_BYTES)     // 147456
#define NTHREADS 256

// pooling fused into GEMM: 400 CTAs x 8 rows, 120 row-steps, 4 per iteration
#define PROWS 8
#define PSTEPS (PROWS * LL)          // 120
#define PGROUP 4

// fp16(rna) copies of A and W; split partial scratch; 1/len; tile counters
__device__ __half g_Ah[GM * GK];
__device__ __half g_Wh[GN * GK];
__device__ float g_part0[GM * GN];
__device__ float g_part1[GM * GN];
__device__ float g_invlen[GM];
__device__ int g_cnt[256];   // zero-init; each counter returns to 0 every launch

__device__ __forceinline__ void mma_f16(float& c0, float& c1, float& c2, float& c3,
                                        uint32_t a0, uint32_t a1, uint32_t a2, uint32_t a3,
                                        uint32_t b0, uint32_t b1) {
    asm volatile(
        "mma.sync.aligned.m16n8k16.row.col.f32.f16.f16.f32 "
        "{%0,%1,%2,%3}, {%4,%5,%6,%7}, {%8,%9}, {%0,%1,%2,%3};\n"
        : "+f"(c0), "+f"(c1), "+f"(c2), "+f"(c3)
        : "r"(a0), "r"(a1), "r"(a2), "r"(a3), "r"(b0), "r"(b1));
}

__device__ __forceinline__ uint32_t smem_u32(const void* p) {
    uint32_t a;
    asm("{ .reg .u64 t; cvta.to.shared.u64 t, %1; cvt.u32.u64 %0, t; }" : "=r"(a) : "l"(p));
    return a;
}

#define CP_ASYNC16(dst, src) \
    asm volatile("cp.async.cg.shared.global [%0], [%1], 16;" :: "r"(dst), "l"(src) : "memory")
#define CP_COMMIT() asm volatile("cp.async.commit_group;" ::: "memory")
#define CP_WAIT(n) asm volatile("cp.async.wait_group %0;" :: "n"(n) : "memory")

#define LDSM4(r0, r1, r2, r3, addr) \
    asm volatile("ldmatrix.sync.aligned.m8n8.x4.shared.b16 {%0,%1,%2,%3}, [%4];" \
                 : "=r"(r0), "=r"(r1), "=r"(r2), "=r"(r3) : "r"(addr))

// ─────────────────── prepass: fp32 -> fp16(rna), plus 1/len ───────────────────
__global__ void __launch_bounds__(256)
cvt_f16_kernel(const float* __restrict__ A, const float* __restrict__ W,
               const int* __restrict__ lens) {
    const int gid = blockIdx.x * blockDim.x + threadIdx.x;
    if (gid < GM) g_invlen[gid] = 1.0f / (float)__ldg(lens + gid);

    const int na8 = GM * GK / 8;   // 16B output chunks for A
    const int nw8 = GN * GK / 8;
    const int total = na8 + nw8;
    for (int i = gid; i < total; i += gridDim.x * blockDim.x) {
        const float4* src;
        uint4* dst;
        if (i < na8) {
            src = (const float4*)A + (size_t)i * 2;
            dst = (uint4*)g_Ah + i;
        } else {
            src = (const float4*)W + (size_t)(i - na8) * 2;
            dst = (uint4*)g_Wh + (i - na8);
        }
        float4 v0 = __ldg(src);
        float4 v1 = __ldg(src + 1);
        __half2 h0 = __floats2half2_rn(v0.x, v0.y);
        __half2 h1 = __floats2half2_rn(v0.z, v0.w);
        __half2 h2 = __floats2half2_rn(v1.x, v1.y);
        __half2 h3 = __floats2half2_rn(v1.z, v1.w);
        uint4 o4;
        o4.x = *(uint32_t*)&h0;
        o4.y = *(uint32_t*)&h1;
        o4.z = *(uint32_t*)&h2;
        o4.w = *(uint32_t*)&h3;
        *dst = o4;
    }
}

// ── GEMM partials (fp16 in, fp32 acc), split-K=2, fused mean-pool + fused reduce ──
__global__ void __launch_bounds__(NTHREADS, 1)
gemm_partial_kernel(const float* __restrict__ phrases, const float* __restrict__ bias,
                    float* __restrict__ out) {
    extern __shared__ char smem[];
    const uint32_t sb = smem_u32(smem);

    const int tid = threadIdx.x;
    const int warp = tid >> 5;      // 0..7
    const int lane = tid & 31;
    const int warp_m = warp & 1;    // 0..1 -> 64-row slab
    const int warp_n = warp >> 1;   // 0..3 -> 32-col slab
    const int m0 = blockIdx.y * BM;
    const int n0 = blockIdx.x * BN;
    const int kbase = blockIdx.z * KHALF;

    // pooling assignment: CTA linear id -> 8 phrase rows
    const int cid = blockIdx.z * (GN / BN) * (GM / BM) + blockIdx.y * (GN / BN) + blockIdx.x;
    const int prow0 = cid * PROWS;
    const float4* pf = (const float4*)(phrases + (size_t)prow0 * LL * DD) + tid;

    // cp.async mappings: tile = 128 rows x 8 16B-chunks (64 halves); 4 chunks/thread each
    uint32_t a_dst[4], b_dst[4];
    const __half* a_src[4];
    const __half* b_src[4];
#pragma unroll
    for (int i = 0; i < 4; i++) {
        int id = tid + i * NTHREADS;     // 0..1023
        int row = id >> 3, c8 = id & 7;
        a_dst[i] = row * (APH * 2) + c8 * 16;
        b_dst[i] = A_STAGE_BYTES + row * (APH * 2) + c8 * 16;
        a_src[i] = g_Ah + (size_t)(m0 + row) * GK + kbase + c8 * 8;
        b_src[i] = g_Wh + (size_t)(n0 + row) * GK + kbase + c8 * 8;
    }

    // ldmatrix lane bases (byte offsets within a stage)
    const int la_row = (lane & 7) + ((lane >> 3) & 1) * 8;
    const uint32_t pA_base = ((warp_m * 64 + la_row) * APH + (lane >> 4) * 8) * 2;
    const int lb_row = (lane & 7) + ((lane >> 4) & 1) * 8;
    const uint32_t pB_base =
        A_STAGE_BYTES + ((warp_n * 32 + lb_row) * APH + ((lane >> 3) & 1) * 8) * 2;

    float acc[4][4][4];
#pragma unroll
    for (int tm = 0; tm < 4; tm++)
#pragma unroll
        for (int tn = 0; tn < 4; tn++)
#pragma unroll
            for (int r = 0; r < 4; r++) acc[tm][tn][r] = 0.0f;

    // preload stages 0..STAGES-2
#pragma unroll
    for (int s = 0; s < STAGES - 1; s++) {
        const uint32_t st = sb + s * STAGE_BYTES;
        const int k0 = s * BK;
#pragma unroll
        for (int i = 0; i < 4; i++) {
            CP_ASYNC16(st + a_dst[i], a_src[i] + k0);
            CP_ASYNC16(st + b_dst[i], b_src[i] + k0);
        }
        CP_COMMIT();
    }

    // pool state: prefetch group 0 (steps 0..3)
    float4 pbuf[PGROUP];
#pragma unroll
    for (int j = 0; j < PGROUP; j++) pbuf[j] = __ldg(pf + j * (DD / 4));
    float pacc0 = 0.f, pacc1 = 0.f, pacc2 = 0.f, pacc3 = 0.f;
    float pinv = 0.f;
    int parow = 0, ppl = 0;

    uint32_t af[2][4][4], bf[2][4][2];

    for (int it = 0; it < NIT; it++) {
        CP_WAIT(STAGES - 2);
        __syncthreads();

        // issue loads for stage it+STAGES-1
        {
            const int ld = it + STAGES - 1;
            if (ld < NIT) {
                const uint32_t st = sb + (ld & (STAGES - 1)) * STAGE_BYTES;
                const int k0 = ld * BK;
#pragma unroll
                for (int i = 0; i < 4; i++) {
                    CP_ASYNC16(st + a_dst[i], a_src[i] + k0);
                    CP_ASYNC16(st + b_dst[i], b_src[i] + k0);
                }
            }
            CP_COMMIT();
        }

        // ── fused pooling: accumulate group `it` (already in pbuf), then prefetch it+1 ──
        if (it * PGROUP < PSTEPS) {
#pragma unroll
            for (int j = 0; j < PGROUP; j++) {
                if (ppl == 0) pinv = __ldg(g_invlen + prow0 + parow);
                pacc0 += pbuf[j].x; pacc1 += pbuf[j].y;
                pacc2 += pbuf[j].z; pacc3 += pbuf[j].w;
                ppl++;
                if (ppl == LL) {
                    float4 r = make_float4(pacc0 * pinv, pacc1 * pinv, pacc2 * pinv, pacc3 * pinv);
                    *((float4*)(out + (size_t)(prow0 + parow) * (2 * GN) + GN) + tid) = r;
                    pacc0 = pacc1 = pacc2 = pacc3 = 0.f;
                    ppl = 0;
                    parow++;
                }
            }
            const int sbase = (it + 1) * PGROUP;
            if (sbase < PSTEPS) {
#pragma unroll
                for (int j = 0; j < PGROUP; j++)
                    pbuf[j] = __ldg(pf + (sbase + j) * (DD / 4));
            }
        }

        const uint32_t st = sb + (it & (STAGES - 1)) * STAGE_BYTES;
        const uint32_t aA = st + pA_base;
        const uint32_t aB = st + pB_base;

        // prefetch fragments for ks=0
#pragma unroll
        for (int tm = 0; tm < 4; tm++)
            LDSM4(af[0][tm][0], af[0][tm][1], af[0][tm][2], af[0][tm][3],
                  aA + (tm * 16 * APH) * 2);
#pragma unroll
        for (int pr = 0; pr < 2; pr++)
            LDSM4(bf[0][pr * 2][0], bf[0][pr * 2][1], bf[0][pr * 2 + 1][0], bf[0][pr * 2 + 1][1],
                  aB + (pr * 16 * APH) * 2);

        // 4 k16-steps, register double-buffered
#pragma unroll
        for (int ks = 0; ks < 4; ks++) {
            const int cur = ks & 1, nxt = cur ^ 1;
            if (ks < 3) {
                const uint32_t ko = (ks + 1) * 32;  // 16 halves = 32 bytes
#pragma unroll
                for (int tm = 0; tm < 4; tm++)
                    LDSM4(af[nxt][tm][0], af[nxt][tm][1], af[nxt][tm][2], af[nxt][tm][3],
                          aA + (tm * 16 * APH) * 2 + ko);
#pragma unroll
                for (int pr = 0; pr < 2; pr++)
                    LDSM4(bf[nxt][pr * 2][0], bf[nxt][pr * 2][1],
                          bf[nxt][pr * 2 + 1][0], bf[nxt][pr * 2 + 1][1],
                          aB + (pr * 16 * APH) * 2 + ko);
            }
#pragma unroll
            for (int tm = 0; tm < 4; tm++)
#pragma unroll
                for (int tn = 0; tn < 4; tn++)
                    mma_f16(acc[tm][tn][0], acc[tm][tn][1], acc[tm][tn][2], acc[tm][tn][3],
                            af[cur][tm][0], af[cur][tm][1], af[cur][tm][2], af[cur][tm][3],
                            bf[cur][tn][0], bf[cur][tn][1]);
        }
    }

    // write raw partial to split scratch
    float* pdst = (blockIdx.z == 0) ? g_part0 : g_part1;
#pragma unroll
    for (int tn = 0; tn < 4; tn++) {
        const int n = n0 + warp_n * 32 + tn * 8 + (lane & 3) * 2;
#pragma unroll
        for (int tm = 0; tm < 4; tm++) {
            const int r0 = m0 + warp_m * 64 + tm * 16 + (lane >> 2);
            *(float2*)(pdst + (size_t)r0 * GN + n) = make_float2(acc[tm][tn][0], acc[tm][tn][1]);
            *(float2*)(pdst + (size_t)(r0 + 8) * GN + n) = make_float2(acc[tm][tn][2], acc[tm][tn][3]);
        }
    }

    // fused split-K reduce: second finisher per tile does relu(p0+p1+b) -> out
    __threadfence();
    __syncthreads();
    int* flag = (int*)smem;   // smem reuse is safe: mainloop fully done
    const int tile = blockIdx.y * (GN / BN) + blockIdx.x;
    if (tid == 0) {
        int old = atomicAdd(&g_cnt[tile], 1);
        *flag = (old == 1);
    }
    __syncthreads();
    if (*flag) {
        __threadfence();  // acquire side: order partial reads after counter observation
#pragma unroll
        for (int i = 0; i < 16; i++) {
            int idx = tid + i * NTHREADS;        // 0..4095 float4s of the 128x128 tile
            int row = idx >> 5, c4 = idx & 31;
            size_t po = (size_t)(m0 + row) * GN + n0 + c4 * 4;
            float4 p0 = *(const float4*)(g_part0 + po);
            float4 p1 = *(const float4*)(g_part1 + po);
            float4 bv = __ldg((const float4*)(bias + n0) + c4);
            float4 v;
            v.x = fmaxf(p0.x + p1.x + bv.x, 0.0f);
            v.y = fmaxf(p0.y + p1.y + bv.y, 0.0f);
            v.z = fmaxf(p0.z + p1.z + bv.z, 0.0f);
            v.w = fmaxf(p0.w + p1.w + bv.w, 0.0f);
            *(float4*)(out + (size_t)(m0 + row) * (2 * GN) + n0 + c4 * 4) = v;
        }
        if (tid == 0) g_cnt[tile] = 0;   // reset for next launch / graph replay
    }
}

extern "C" void kernel_launch(void* const* d_in, const int* in_sizes, int n_in,
                              void* d_out, int out_size) {
    const float* features = (const float*)d_in[0];
    const float* phrases  = (const float*)d_in[1];
    const float* W        = (const float*)d_in[2];
    const float* bias     = (const float*)d_in[3];
    const int*   lens     = (const int*)d_in[4];
    float* out = (float*)d_out;

    cvt_f16_kernel<<<2048, 256>>>(features, W, lens);

    cudaFuncSetAttribute(gemm_partial_kernel, cudaFuncAttributeMaxDynamicSharedMemorySize,
                         SMEM_TOTAL);
    dim3 ggrid(GN / BN, GM / BM, KSPLIT);  // (8, 25, 2) = 400 CTAs
    gemm_partial_kernel<<<ggrid, NTHREADS, SMEM_TOTAL>>>(phrases, bias, out);
}

// round 10
// speedup vs baseline: 1.9514x; 1.0862x over previous
#include <cuda_runtime.h>
#include <cuda_fp16.h>
#include <cstdint>

// Problem dims
#define BB 64
#define RR 50
#define LL 15
#define DD 1024
#define FF 4096

// GEMM: M=B*R=3200, N=D=1024, K=F=4096
#define GM 3200
#define GN 1024
#define GK 4096

// CTA tile 64x128x64 (fp16), split-K=2 -> grid (8, 50, 2) = 800 CTAs, 2 CTAs/SM.
#define BM 64
#define BN 128
#define BK 64
#define KSPLIT 2
#define KHALF (GK / KSPLIT)         // 2048
#define NIT (KHALF / BK)            // 32
#define APH 72                      // padded row stride in halves (144B, conflict-free)
#define STAGES 4
#define A_STAGE_BYTES (BM * APH * 2)          // 9216
#define STAGE_BYTES (A_STAGE_BYTES + BN * APH * 2)   // 27648
#define SMEM_TOTAL (STAGES * STAGE_BYTES)     // 110592 -> 2 CTAs/SM
#define NTHREADS 256

// pooling fused into GEMM: 800 CTAs x 4 rows, 60 row-steps, 2 per iteration
#define PROWS 4
#define PSTEPS (PROWS * LL)          // 60
#define PGROUP 2

// fp16(rna) copies of A and W; split partial scratch; 1/len
__device__ __half g_Ah[GM * GK];
__device__ __half g_Wh[GN * GK];
__device__ float g_part0[GM * GN];
__device__ float g_part1[GM * GN];
__device__ float g_invlen[GM];

__device__ __forceinline__ void mma_f16(float& c0, float& c1, float& c2, float& c3,
                                        uint32_t a0, uint32_t a1, uint32_t a2, uint32_t a3,
                                        uint32_t b0, uint32_t b1) {
    asm volatile(
        "mma.sync.aligned.m16n8k16.row.col.f32.f16.f16.f32 "
        "{%0,%1,%2,%3}, {%4,%5,%6,%7}, {%8,%9}, {%0,%1,%2,%3};\n"
        : "+f"(c0), "+f"(c1), "+f"(c2), "+f"(c3)
        : "r"(a0), "r"(a1), "r"(a2), "r"(a3), "r"(b0), "r"(b1));
}

__device__ __forceinline__ uint32_t smem_u32(const void* p) {
    uint32_t a;
    asm("{ .reg .u64 t; cvta.to.shared.u64 t, %1; cvt.u32.u64 %0, t; }" : "=r"(a) : "l"(p));
    return a;
}

#define CP_ASYNC16(dst, src) \
    asm volatile("cp.async.cg.shared.global [%0], [%1], 16;" :: "r"(dst), "l"(src) : "memory")
#define CP_COMMIT() asm volatile("cp.async.commit_group;" ::: "memory")
#define CP_WAIT(n) asm volatile("cp.async.wait_group %0;" :: "n"(n) : "memory")

#define LDSM4(r0, r1, r2, r3, addr) \
    asm volatile("ldmatrix.sync.aligned.m8n8.x4.shared.b16 {%0,%1,%2,%3}, [%4];" \
                 : "=r"(r0), "=r"(r1), "=r"(r2), "=r"(r3) : "r"(addr))

// ─────────────────── prepass: fp32 -> fp16(rna), plus 1/len ───────────────────
__global__ void __launch_bounds__(256)
cvt_f16_kernel(const float* __restrict__ A, const float* __restrict__ W,
               const int* __restrict__ lens) {
    const int gid = blockIdx.x * blockDim.x + threadIdx.x;
    if (gid < GM) g_invlen[gid] = 1.0f / (float)__ldg(lens + gid);

    const int na8 = GM * GK / 8;   // 16B output chunks for A
    const int nw8 = GN * GK / 8;
    const int total = na8 + nw8;
    for (int i = gid; i < total; i += gridDim.x * blockDim.x) {
        const float4* src;
        uint4* dst;
        if (i < na8) {
            src = (const float4*)A + (size_t)i * 2;
            dst = (uint4*)g_Ah + i;
        } else {
            src = (const float4*)W + (size_t)(i - na8) * 2;
            dst = (uint4*)g_Wh + (i - na8);
        }
        float4 v0 = __ldg(src);
        float4 v1 = __ldg(src + 1);
        __half2 h0 = __floats2half2_rn(v0.x, v0.y);
        __half2 h1 = __floats2half2_rn(v0.z, v0.w);
        __half2 h2 = __floats2half2_rn(v1.x, v1.y);
        __half2 h3 = __floats2half2_rn(v1.z, v1.w);
        uint4 o4;
        o4.x = *(uint32_t*)&h0;
        o4.y = *(uint32_t*)&h1;
        o4.z = *(uint32_t*)&h2;
        o4.w = *(uint32_t*)&h3;
        *dst = o4;
    }
}

// ── GEMM partials (fp16 in, fp32 acc), split-K=2, 2 CTAs/SM, fused mean-pool ──
__global__ void __launch_bounds__(NTHREADS, 2)
gemm_partial_kernel(const float* __restrict__ phrases, float* __restrict__ out) {
    extern __shared__ char smem[];
    const uint32_t sb = smem_u32(smem);

    const int tid = threadIdx.x;
    const int warp = tid >> 5;      // 0..7
    const int lane = tid & 31;
    const int warp_m = warp & 1;    // 0..1 -> 32-row slab
    const int warp_n = warp >> 1;   // 0..3 -> 32-col slab
    const int m0 = blockIdx.y * BM;
    const int n0 = blockIdx.x * BN;
    const int kbase = blockIdx.z * KHALF;

    // pooling assignment: CTA linear id -> 4 phrase rows
    const int cid = blockIdx.z * (GN / BN) * (GM / BM) + blockIdx.y * (GN / BN) + blockIdx.x;
    const int prow0 = cid * PROWS;
    const float4* pf = (const float4*)(phrases + (size_t)prow0 * LL * DD) + tid;

    // cp.async mappings: A = 64 rows x 8 chunks -> 2/thread; B = 128 x 8 -> 4/thread
    uint32_t a_dst[2], b_dst[4];
    const __half* a_src[2];
    const __half* b_src[4];
#pragma unroll
    for (int i = 0; i < 2; i++) {
        int id = tid + i * NTHREADS;     // 0..511
        int row = id >> 3, c8 = id & 7;
        a_dst[i] = row * (APH * 2) + c8 * 16;
        a_src[i] = g_Ah + (size_t)(m0 + row) * GK + kbase + c8 * 8;
    }
#pragma unroll
    for (int i = 0; i < 4; i++) {
        int id = tid + i * NTHREADS;     // 0..1023
        int row = id >> 3, c8 = id & 7;
        b_dst[i] = A_STAGE_BYTES + row * (APH * 2) + c8 * 16;
        b_src[i] = g_Wh + (size_t)(n0 + row) * GK + kbase + c8 * 8;
    }

    // ldmatrix lane bases (byte offsets within a stage)
    const int la_row = (lane & 7) + ((lane >> 3) & 1) * 8;
    const uint32_t pA_base = ((warp_m * 32 + la_row) * APH + (lane >> 4) * 8) * 2;
    const int lb_row = (lane & 7) + ((lane >> 4) & 1) * 8;
    const uint32_t pB_base =
        A_STAGE_BYTES + ((warp_n * 32 + lb_row) * APH + ((lane >> 3) & 1) * 8) * 2;

    float acc[2][4][4];
#pragma unroll
    for (int tm = 0; tm < 2; tm++)
#pragma unroll
        for (int tn = 0; tn < 4; tn++)
#pragma unroll
            for (int r = 0; r < 4; r++) acc[tm][tn][r] = 0.0f;

    // preload stages 0..STAGES-2
#pragma unroll
    for (int s = 0; s < STAGES - 1; s++) {
        const uint32_t st = sb + s * STAGE_BYTES;
        const int k0 = s * BK;
#pragma unroll
        for (int i = 0; i < 2; i++) CP_ASYNC16(st + a_dst[i], a_src[i] + k0);
#pragma unroll
        for (int i = 0; i < 4; i++) CP_ASYNC16(st + b_dst[i], b_src[i] + k0);
        CP_COMMIT();
    }

    // pool state: prefetch group 0
    float4 pbuf[PGROUP];
#pragma unroll
    for (int j = 0; j < PGROUP; j++) pbuf[j] = __ldg(pf + j * (DD / 4));
    float pacc0 = 0.f, pacc1 = 0.f, pacc2 = 0.f, pacc3 = 0.f;
    float pinv = 0.f;
    int parow = 0, ppl = 0;

    uint32_t af[2][2][4], bf[2][4][2];

    for (int it = 0; it < NIT; it++) {
        CP_WAIT(STAGES - 2);
        __syncthreads();

        // issue loads for stage it+STAGES-1
        {
            const int ld = it + STAGES - 1;
            if (ld < NIT) {
                const uint32_t st = sb + (ld & (STAGES - 1)) * STAGE_BYTES;
                const int k0 = ld * BK;
#pragma unroll
                for (int i = 0; i < 2; i++) CP_ASYNC16(st + a_dst[i], a_src[i] + k0);
#pragma unroll
                for (int i = 0; i < 4; i++) CP_ASYNC16(st + b_dst[i], b_src[i] + k0);
            }
            CP_COMMIT();
        }

        // fused pooling: accumulate group `it`, prefetch group it+1
        if (it * PGROUP < PSTEPS) {
#pragma unroll
            for (int j = 0; j < PGROUP; j++) {
                if (ppl == 0) pinv = __ldg(g_invlen + prow0 + parow);
                pacc0 += pbuf[j].x; pacc1 += pbuf[j].y;
                pacc2 += pbuf[j].z; pacc3 += pbuf[j].w;
                ppl++;
                if (ppl == LL) {
                    float4 r = make_float4(pacc0 * pinv, pacc1 * pinv, pacc2 * pinv, pacc3 * pinv);
                    *((float4*)(out + (size_t)(prow0 + parow) * (2 * GN) + GN) + tid) = r;
                    pacc0 = pacc1 = pacc2 = pacc3 = 0.f;
                    ppl = 0;
                    parow++;
                }
            }
            const int sbase = (it + 1) * PGROUP;
            if (sbase < PSTEPS) {
#pragma unroll
                for (int j = 0; j < PGROUP; j++)
                    pbuf[j] = __ldg(pf + (sbase + j) * (DD / 4));
            }
        }

        const uint32_t st = sb + (it & (STAGES - 1)) * STAGE_BYTES;
        const uint32_t aA = st + pA_base;
        const uint32_t aB = st + pB_base;

        // prefetch fragments for ks=0
#pragma unroll
        for (int tm = 0; tm < 2; tm++)
            LDSM4(af[0][tm][0], af[0][tm][1], af[0][tm][2], af[0][tm][3],
                  aA + (tm * 16 * APH) * 2);
#pragma unroll
        for (int pr = 0; pr < 2; pr++)
            LDSM4(bf[0][pr * 2][0], bf[0][pr * 2][1], bf[0][pr * 2 + 1][0], bf[0][pr * 2 + 1][1],
                  aB + (pr * 16 * APH) * 2);

        // 4 k16-steps, register double-buffered
#pragma unroll
        for (int ks = 0; ks < 4; ks++) {
            const int cur = ks & 1, nxt = cur ^ 1;
            if (ks < 3) {
                const uint32_t ko = (ks + 1) * 32;  // 16 halves = 32 bytes
#pragma unroll
                for (int tm = 0; tm < 2; tm++)
                    LDSM4(af[nxt][tm][0], af[nxt][tm][1], af[nxt][tm][2], af[nxt][tm][3],
                          aA + (tm * 16 * APH) * 2 + ko);
#pragma unroll
                for (int pr = 0; pr < 2; pr++)
                    LDSM4(bf[nxt][pr * 2][0], bf[nxt][pr * 2][1],
                          bf[nxt][pr * 2 + 1][0], bf[nxt][pr * 2 + 1][1],
                          aB + (pr * 16 * APH) * 2 + ko);
            }
#pragma unroll
            for (int tm = 0; tm < 2; tm++)
#pragma unroll
                for (int tn = 0; tn < 4; tn++)
                    mma_f16(acc[tm][tn][0], acc[tm][tn][1], acc[tm][tn][2], acc[tm][tn][3],
                            af[cur][tm][0], af[cur][tm][1], af[cur][tm][2], af[cur][tm][3],
                            bf[cur][tn][0], bf[cur][tn][1]);
        }
    }

    // write raw partial to split scratch
    float* pdst = (blockIdx.z == 0) ? g_part0 : g_part1;
#pragma unroll
    for (int tn = 0; tn < 4; tn++) {
        const int n = n0 + warp_n * 32 + tn * 8 + (lane & 3) * 2;
#pragma unroll
        for (int tm = 0; tm < 2; tm++) {
            const int r0 = m0 + warp_m * 32 + tm * 16 + (lane >> 2);
            *(float2*)(pdst + (size_t)r0 * GN + n) = make_float2(acc[tm][tn][0], acc[tm][tn][1]);
            *(float2*)(pdst + (size_t)(r0 + 8) * GN + n) = make_float2(acc[tm][tn][2], acc[tm][tn][3]);
        }
    }
}

// ─────────────── reduce: out[:,0:1024] = relu(p0 + p1 + bias) ───────────────
__global__ void __launch_bounds__(256)
reduce_kernel(const float* __restrict__ bias, float* __restrict__ out) {
    const int row = blockIdx.x;
    const int t = threadIdx.x;                 // 0..255 -> float4 within 1024 cols
    float4* o = (float4*)(out + (size_t)row * (2 * GN)) + t;
    float4 p0 = __ldg((const float4*)(g_part0 + (size_t)row * GN) + t);
    float4 p1 = __ldg((const float4*)(g_part1 + (size_t)row * GN) + t);
    float4 bv = __ldg((const float4*)bias + t);
    float4 v;
    v.x = fmaxf(p0.x + p1.x + bv.x, 0.0f);
    v.y = fmaxf(p0.y + p1.y + bv.y, 0.0f);
    v.z = fmaxf(p0.z + p1.z + bv.z, 0.0f);
    v.w = fmaxf(p0.w + p1.w + bv.w, 0.0f);
    *o = v;
}

extern "C" void kernel_launch(void* const* d_in, const int* in_sizes, int n_in,
                              void* d_out, int out_size) {
    const float* features = (const float*)d_in[0];
    const float* phrases  = (const float*)d_in[1];
    const float* W        = (const float*)d_in[2];
    const float* bias     = (const float*)d_in[3];
    const int*   lens     = (const int*)d_in[4];
    float* out = (float*)d_out;

    cvt_f16_kernel<<<2048, 256>>>(features, W, lens);

    cudaFuncSetAttribute(gemm_partial_kernel, cudaFuncAttributeMaxDynamicSharedMemorySize,
                         SMEM_TOTAL);
    dim3 ggrid(GN / BN, GM / BM, KSPLIT);  // (8, 50, 2) = 800 CTAs
    gemm_partial_kernel<<<ggrid, NTHREADS, SMEM_TOTAL>>>(phrases, out);

    reduce_kernel<<<GM, 256>>>(bias, out);
}